// round 1
// baseline (speedup 1.0000x reference)
#include <cuda_runtime.h>
#include <math.h>

#define MAXN 4096
#define MARGIN 0.3f
#define BIGF 1000000.0f

// Scratch (no cudaMalloc allowed) — re-initialized every launch for graph determinism.
__device__ float    g_sq[MAXN];
__device__ unsigned g_hp[MAXN];      // hardest-positive dist per row (fp32 bits)
__device__ unsigned g_hnfb[MAXN];    // hardest (farthest) negative per row
__device__ unsigned g_hnsemi[MAXN];  // closest semi-hard negative per row
__device__ int      g_semicnt;       // global count of semi-hard pairs

__global__ void init_kernel(int n) {
    int i = blockIdx.x * blockDim.x + threadIdx.x;
    if (i < n) {
        g_hp[i] = 0u;
        g_hnfb[i] = 0u;
        g_hnsemi[i] = __float_as_uint(BIGF);
    }
    if (i == 0) g_semicnt = 0;
}

__global__ void sq_kernel(const float* __restrict__ E, int d) {
    int row = blockIdx.x;
    const float4* p = (const float4*)(E + (size_t)row * d);
    int d4 = d >> 2;
    float s = 0.f;
    for (int c = threadIdx.x; c < d4; c += blockDim.x) {
        float4 v = p[c];
        s += v.x * v.x + v.y * v.y + v.z * v.z + v.w * v.w;
    }
    for (int o = 16; o; o >>= 1) s += __shfl_down_sync(0xffffffffu, s, o);
    __shared__ float ws[8];
    int lane = threadIdx.x & 31, w = threadIdx.x >> 5;
    if (lane == 0) ws[w] = s;
    __syncthreads();
    if (threadIdx.x == 0) {
        float t = 0.f;
        int nw = blockDim.x >> 5;
        for (int k = 0; k < nw; k++) t += ws[k];
        g_sq[row] = t;
    }
}

// 128x128 distance tile, fused row reductions.
// PASS 1: hp[i] = max over positives of dist(i,j)
// PASS 2: hnfb[i] = max over negatives; hnsemi[i] = min over semi-hard negatives;
//         g_semicnt += #semi-hard entries
template <int PASS>
__global__ __launch_bounds__(256) void dist_kernel(const float* __restrict__ E,
                                                   const int* __restrict__ labels,
                                                   int n, int d) {
    __shared__ float As[16][128];
    __shared__ float Bs[16][128];
    __shared__ int lrow[128], lcol[128];
    __shared__ unsigned srmax[128];
    __shared__ unsigned srmin[128];
    __shared__ float shp[128];
    __shared__ int scnt;

    int rowBase = blockIdx.y * 128;
    int colBase = blockIdx.x * 128;
    int tid = threadIdx.x;
    int tx = tid & 15;   // N dim, 8 cols each
    int ty = tid >> 4;   // M dim, 8 rows each

    if (tid < 128) {
        lrow[tid] = labels[rowBase + tid];
        lcol[tid] = labels[colBase + tid];
        srmax[tid] = 0u;
        srmin[tid] = __float_as_uint(BIGF);
        if (PASS == 2) shp[tid] = __uint_as_float(g_hp[rowBase + tid]);
    }
    if (tid == 0) scnt = 0;

    float acc[8][8];
#pragma unroll
    for (int m = 0; m < 8; m++)
#pragma unroll
        for (int nn = 0; nn < 8; nn++) acc[m][nn] = 0.f;

    for (int k0 = 0; k0 < d; k0 += 16) {
        __syncthreads();
        for (int t = tid; t < 512; t += 256) {
            int r = t >> 2, seg = t & 3;
            const float4 va = *(const float4*)(E + (size_t)(rowBase + r) * d + k0 + seg * 4);
            As[seg * 4 + 0][r] = va.x; As[seg * 4 + 1][r] = va.y;
            As[seg * 4 + 2][r] = va.z; As[seg * 4 + 3][r] = va.w;
            const float4 vb = *(const float4*)(E + (size_t)(colBase + r) * d + k0 + seg * 4);
            Bs[seg * 4 + 0][r] = vb.x; Bs[seg * 4 + 1][r] = vb.y;
            Bs[seg * 4 + 2][r] = vb.z; Bs[seg * 4 + 3][r] = vb.w;
        }
        __syncthreads();
#pragma unroll
        for (int kk = 0; kk < 16; kk++) {
            float a[8], b[8];
#pragma unroll
            for (int m = 0; m < 8; m++) a[m] = As[kk][ty * 8 + m];
#pragma unroll
            for (int nn = 0; nn < 8; nn++) b[nn] = Bs[kk][tx * 8 + nn];
#pragma unroll
            for (int m = 0; m < 8; m++)
#pragma unroll
                for (int nn = 0; nn < 8; nn++) acc[m][nn] += a[m] * b[nn];
        }
    }

    // Epilogue: distances + masked row reductions
    float sqrow[8], sqcol[8];
    int lr[8], lc[8];
#pragma unroll
    for (int m = 0; m < 8; m++) {
        sqrow[m] = g_sq[rowBase + ty * 8 + m];
        lr[m] = lrow[ty * 8 + m];
    }
#pragma unroll
    for (int nn = 0; nn < 8; nn++) {
        sqcol[nn] = g_sq[colBase + tx * 8 + nn];
        lc[nn] = lcol[tx * 8 + nn];
    }

    int localcnt = 0;
#pragma unroll
    for (int m = 0; m < 8; m++) {
        float hp = (PASS == 2) ? shp[ty * 8 + m] : 0.f;
        float mmax = 0.f;
        float mmin = BIGF;
#pragma unroll
        for (int nn = 0; nn < 8; nn++) {
            float d2 = sqrow[m] + sqcol[nn] - 2.f * acc[m][nn];
            float dist = sqrtf(fmaxf(d2, 1e-12f));
            bool pos = (lr[m] == lc[nn]);
            if (PASS == 1) {
                if (pos) mmax = fmaxf(mmax, dist);
            } else {
                if (!pos) {
                    mmax = fmaxf(mmax, dist);
                    if (dist > hp && dist < hp + MARGIN) {
                        mmin = fminf(mmin, dist);
                        localcnt++;
                    }
                }
            }
        }
        if (mmax > 0.f) atomicMax(&srmax[ty * 8 + m], __float_as_uint(mmax));
        if (PASS == 2 && mmin < BIGF) atomicMin(&srmin[ty * 8 + m], __float_as_uint(mmin));
    }
    if (PASS == 2 && localcnt) atomicAdd(&scnt, localcnt);
    __syncthreads();

    if (tid < 128) {
        if (PASS == 1) {
            atomicMax(&g_hp[rowBase + tid], srmax[tid]);
        } else {
            atomicMax(&g_hnfb[rowBase + tid], srmax[tid]);
            atomicMin(&g_hnsemi[rowBase + tid], srmin[tid]);
        }
    }
    if (PASS == 2 && tid == 0 && scnt) atomicAdd(&g_semicnt, scnt);
}

__global__ void finalize_kernel(float* __restrict__ out, int n) {
    bool useSemi = (g_semicnt > 0);
    float sum = 0.f;
    int cnt = 0;
    for (int i = threadIdx.x; i < n; i += blockDim.x) {
        float hp = __uint_as_float(g_hp[i]);
        float hn = useSemi ? __uint_as_float(g_hnsemi[i]) : __uint_as_float(g_hnfb[i]);
        float t = hp - hn + MARGIN;
        if (t < 0.f) t = 0.f;
        sum += t;
        if (t > 0.f) cnt++;
    }
    for (int o = 16; o; o >>= 1) {
        sum += __shfl_down_sync(0xffffffffu, sum, o);
        cnt += __shfl_down_sync(0xffffffffu, cnt, o);
    }
    __shared__ float wsum[32];
    __shared__ int wcnt[32];
    int lane = threadIdx.x & 31, w = threadIdx.x >> 5;
    if (lane == 0) { wsum[w] = sum; wcnt[w] = cnt; }
    __syncthreads();
    if (threadIdx.x == 0) {
        float s = 0.f; int c = 0;
        int nw = blockDim.x >> 5;
        for (int k = 0; k < nw; k++) { s += wsum[k]; c += wcnt[k]; }
        // num_valid > 0: sum / num_valid; else mean(triplet) which is 0.
        out[0] = (c > 0) ? (s / (float)c) : 0.0f;
    }
}

extern "C" void kernel_launch(void* const* d_in, const int* in_sizes, int n_in,
                              void* d_out, int out_size) {
    const float* E = (const float*)d_in[0];
    const int* labels = (const int*)d_in[1];
    int n = in_sizes[1];
    int d = in_sizes[0] / n;

    init_kernel<<<(n + 255) / 256, 256>>>(n);
    sq_kernel<<<n, 128>>>(E, d);
    dim3 grid(n / 128, n / 128);
    dist_kernel<1><<<grid, 256>>>(E, labels, n, d);
    dist_kernel<2><<<grid, 256>>>(E, labels, n, d);
    finalize_kernel<<<1, 1024>>>((float*)d_out, n);
}

// round 3
// speedup vs baseline: 3.8653x; 3.8653x over previous
#include <cuda_runtime.h>
#include <cuda_fp16.h>
#include <cstdint>
#include <math.h>

#define MAXN   4096
#define MAXD   512
#define NB     1024
#define MARGIN 0.3f
#define BIGD2  3.0e38f

// ---------------- scratch ----------------
__device__ __align__(16) __half g_Ehi[MAXN * MAXD];
__device__ __align__(16) __half g_Elo[MAXN * MAXD];
__device__ float    g_sq[MAXN];
__device__ float    g_hp2[MAXN];
__device__ float    g_hpB2[MAXN];
__device__ unsigned g_hnfb[MAXN];
__device__ unsigned g_hnsemi[MAXN];
__device__ int      g_semiflag;
__device__ int      g_ccount[NB];
__device__ int      g_ccur[NB];
__device__ int      g_coff[NB];
__device__ int      g_clist[MAXN];

__device__ __forceinline__ uint32_t smem_u32(const void* p) {
    uint32_t a;
    asm("{ .reg .u64 t; cvta.to.shared.u64 t, %1; cvt.u32.u64 %0, t; }" : "=r"(a) : "l"(p));
    return a;
}

#define CP_ASYNC16(dst, src) \
    asm volatile("cp.async.cg.shared.global [%0], [%1], 16;" :: "r"(dst), "l"(src))
#define CP_COMMIT() asm volatile("cp.async.commit_group;")
#define CP_WAIT1()  asm volatile("cp.async.wait_group 1;")
#define CP_WAIT0()  asm volatile("cp.async.wait_group 0;")

#define LDM4(r0, r1, r2, r3, addr)                                              \
    asm volatile("ldmatrix.sync.aligned.m8n8.x4.shared.b16 {%0,%1,%2,%3}, [%4];" \
        : "=r"(r0), "=r"(r1), "=r"(r2), "=r"(r3) : "r"(addr))

#define MMA16816(c, a, b0, b1)                                                   \
    asm volatile("mma.sync.aligned.m16n8k16.row.col.f32.f16.f16.f32 "            \
        "{%0,%1,%2,%3},{%4,%5,%6,%7},{%8,%9},{%0,%1,%2,%3};"                     \
        : "+f"((c)[0]), "+f"((c)[1]), "+f"((c)[2]), "+f"((c)[3])                 \
        : "r"((a)[0]), "r"((a)[1]), "r"((a)[2]), "r"((a)[3]), "r"(b0), "r"(b1))

// ---------------- small kernels ----------------
__global__ void init_kernel(int n) {
    int i = blockIdx.x * blockDim.x + threadIdx.x;
    if (i < NB) { g_ccount[i] = 0; g_ccur[i] = 0; }
    if (i < n) { g_hnfb[i] = 0u; g_hnsemi[i] = __float_as_uint(BIGD2); }
    if (i == 0) g_semiflag = 0;
}

__global__ void convert_kernel(const float* __restrict__ E, int total) {
    for (int i = blockIdx.x * blockDim.x + threadIdx.x; i < total; i += gridDim.x * blockDim.x) {
        float x = E[i];
        __half h = __float2half(x);
        g_Ehi[i] = h;
        g_Elo[i] = __float2half(x - __half2float(h));
    }
}

__global__ void sq_kernel(const float* __restrict__ E, int d) {
    int row = blockIdx.x;
    const float4* p = (const float4*)(E + (size_t)row * d);
    float s = 0.f;
    for (int c = threadIdx.x; c < (d >> 2); c += blockDim.x) {
        float4 v = p[c];
        s += v.x * v.x + v.y * v.y + v.z * v.z + v.w * v.w;
    }
    for (int o = 16; o; o >>= 1) s += __shfl_xor_sync(0xffffffffu, s, o);
    __shared__ float ws[4];
    int lane = threadIdx.x & 31, w = threadIdx.x >> 5;
    if (lane == 0) ws[w] = s;
    __syncthreads();
    if (threadIdx.x == 0) {
        float t = 0.f;
        for (int k = 0; k < (int)(blockDim.x >> 5); k++) t += ws[k];
        g_sq[row] = t;
    }
}

__global__ void hist_kernel(const int* __restrict__ labels, int n) {
    int i = blockIdx.x * blockDim.x + threadIdx.x;
    if (i < n) atomicAdd(&g_ccount[labels[i] & (NB - 1)], 1);
}

__global__ void scan_kernel() {
    __shared__ int s[NB];
    int t = threadIdx.x;
    int v = g_ccount[t];
    s[t] = v;
    for (int off = 1; off < NB; off <<= 1) {
        __syncthreads();
        int u = (t >= off) ? s[t - off] : 0;
        __syncthreads();
        s[t] += u;
    }
    g_coff[t] = s[t] - v;
}

__global__ void fill_kernel(const int* __restrict__ labels, int n) {
    int i = blockIdx.x * blockDim.x + threadIdx.x;
    if (i < n) {
        int c = labels[i] & (NB - 1);
        int pos = g_coff[c] + atomicAdd(&g_ccur[c], 1);
        g_clist[pos] = i;
    }
}

// Exact fp32 hardest-positive per anchor (one warp per anchor).
__global__ void hp_kernel(const float* __restrict__ E, const int* __restrict__ labels,
                          int n, int d) {
    int w = (blockIdx.x * blockDim.x + threadIdx.x) >> 5;
    int lid = threadIdx.x & 31;
    if (w >= n) return;
    int c = labels[w] & (NB - 1);
    const float* ea = E + (size_t)w * d;
    int dk = d >> 5;
    float a0[MAXD / 32];
#pragma unroll
    for (int j = 0; j < MAXD / 32; j++) if (j < dk) a0[j] = ea[lid + 32 * j];
    int beg = g_coff[c], cnt = g_ccount[c];
    float sqa = g_sq[w];
    float maxd2 = 0.f;
    for (int t = 0; t < cnt; t++) {
        int m = g_clist[beg + t];
        const float* em = E + (size_t)m * d;
        float dot = 0.f;
#pragma unroll
        for (int j = 0; j < MAXD / 32; j++) if (j < dk) dot += a0[j] * em[lid + 32 * j];
        for (int o = 16; o; o >>= 1) dot += __shfl_xor_sync(0xffffffffu, dot, o);
        float d2 = sqa + g_sq[m] - 2.f * dot;
        maxd2 = fmaxf(maxd2, d2);
    }
    if (lid == 0) {
        float h2 = fmaxf(maxd2, 1e-12f);
        g_hp2[w] = h2;
        float hp = sqrtf(h2);
        g_hpB2[w] = (hp + MARGIN) * (hp + MARGIN);
    }
}

// ---------------- HMMA GEMM, lower-triangle tiles, fused 2-sided epilogue ----------------
#define BK     32
#define PITCH  80                 // bytes per smem row (40 halves)
#define TILEB  (128 * PITCH)      // 10240
#define BUFB   (4 * TILEB)        // 40960: Ahi, Alo, Bhi, Blo
#define AUXO   (2 * BUFB)         // 81920
#define SMEM_DYN (AUXO + 6144)

__global__ __launch_bounds__(256, 1) void gemm_kernel(const int* __restrict__ labels,
                                                      int n, int d) {
    extern __shared__ char sm[];
    uint32_t sb = smem_u32(sm);
    int tid = threadIdx.x, lane = tid & 31, wid = tid >> 5;
    int wm = wid >> 2, wn = wid & 3;

    // triangle mapping: bid -> (by, bx), bx <= by
    int bid = blockIdx.x;
    int by = (int)((sqrtf(8.f * (float)bid + 1.f) - 1.f) * 0.5f);
    while ((by + 1) * (by + 2) / 2 <= bid) by++;
    while (by * (by + 1) / 2 > bid) by--;
    int bx = bid - by * (by + 1) / 2;
    int rowBase = by * 128, colBase = bx * 128;

    float*    s_sqc  = (float*)(sm + AUXO);
    int*      s_labc = (int*)(sm + AUXO + 512);
    float*    s_sqr  = (float*)(sm + AUXO + 1024);
    int*      s_labr = (int*)(sm + AUXO + 1536);
    float*    s_hp2r = (float*)(sm + AUXO + 2048);
    float*    s_hpBr = (float*)(sm + AUXO + 2560);
    float*    s_hp2c = (float*)(sm + AUXO + 3072);
    float*    s_hpBc = (float*)(sm + AUXO + 3584);
    unsigned* shRmax = (unsigned*)(sm + AUXO + 4096);
    unsigned* shRmin = (unsigned*)(sm + AUXO + 4608);
    unsigned* shCmax = (unsigned*)(sm + AUXO + 5120);
    unsigned* shCmin = (unsigned*)(sm + AUXO + 5632);

    if (tid < 128) {
        s_sqc[tid]  = g_sq[colBase + tid];  s_labc[tid] = labels[colBase + tid];
        s_sqr[tid]  = g_sq[rowBase + tid];  s_labr[tid] = labels[rowBase + tid];
        s_hp2r[tid] = g_hp2[rowBase + tid]; s_hpBr[tid] = g_hpB2[rowBase + tid];
        s_hp2c[tid] = g_hp2[colBase + tid]; s_hpBc[tid] = g_hpB2[colBase + tid];
        shRmax[tid] = 0u; shRmin[tid] = __float_as_uint(BIGD2);
        shCmax[tid] = 0u; shCmin[tid] = __float_as_uint(BIGD2);
    }

    // per-thread gmem->smem copy slots: 8 x 16B per buffer fill
    const __half* gsrc[8];
    uint32_t sdst[8];
    {
        const __half* tp0 = g_Ehi + (size_t)rowBase * d;
        const __half* tp1 = g_Elo + (size_t)rowBase * d;
        const __half* tp2 = g_Ehi + (size_t)colBase * d;
        const __half* tp3 = g_Elo + (size_t)colBase * d;
        const __half* tps[4] = {tp0, tp1, tp2, tp3};
#pragma unroll
        for (int t = 0; t < 8; t++) {
            int tile = t >> 1;
            int w = ((t & 1) << 8) + tid;   // 0..511
            int r = w >> 2, ch = w & 3;
            gsrc[t] = tps[tile] + (size_t)r * d + ch * 8;
            sdst[t] = sb + tile * TILEB + r * PITCH + ch * 16;
        }
    }

    // ldmatrix per-lane offsets
    uint32_t a_off = (uint32_t)((wm * 64 + (lane & 15)) * PITCH + ((lane >> 4) << 4));
    uint32_t b_off = (uint32_t)((wn * 32 + (lane & 7) + ((lane >> 4) & 1) * 8) * PITCH +
                                (((lane >> 3) & 1) << 4));

    float acc[4][4][4];
#pragma unroll
    for (int im = 0; im < 4; im++)
#pragma unroll
        for (int in = 0; in < 4; in++)
#pragma unroll
            for (int e = 0; e < 4; e++) acc[im][in][e] = 0.f;

    int NC = d / BK;   // 16
    // prologue
#pragma unroll
    for (int t = 0; t < 8; t++) CP_ASYNC16(sdst[t], gsrc[t]);
    CP_COMMIT();

    for (int c = 0; c < NC; c++) {
        int buf = c & 1;
        if (c + 1 < NC) {
            int nb_ = (c + 1) & 1;
            int k0 = (c + 1) * BK;
#pragma unroll
            for (int t = 0; t < 8; t++) CP_ASYNC16(sdst[t] + nb_ * BUFB, gsrc[t] + k0);
            CP_COMMIT();
            CP_WAIT1();
        } else {
            CP_WAIT0();
        }
        __syncthreads();

        uint32_t base = sb + buf * BUFB;
#pragma unroll
        for (int k16 = 0; k16 < 2; k16++) {
            uint32_t ah[4][4], al[4][4], bh[4][2], bl[4][2];
#pragma unroll
            for (int im = 0; im < 4; im++) {
                uint32_t aA = base + im * (16 * PITCH) + k16 * 32 + a_off;
                LDM4(ah[im][0], ah[im][1], ah[im][2], ah[im][3], aA);
                LDM4(al[im][0], al[im][1], al[im][2], al[im][3], aA + TILEB);
            }
#pragma unroll
            for (int p = 0; p < 2; p++) {
                uint32_t aB = base + 2 * TILEB + p * (16 * PITCH) + k16 * 32 + b_off;
                LDM4(bh[2 * p][0], bh[2 * p][1], bh[2 * p + 1][0], bh[2 * p + 1][1], aB);
                LDM4(bl[2 * p][0], bl[2 * p][1], bl[2 * p + 1][0], bl[2 * p + 1][1], aB + TILEB);
            }
#pragma unroll
            for (int im = 0; im < 4; im++)
#pragma unroll
                for (int in = 0; in < 4; in++) {
                    MMA16816(acc[im][in], ah[im], bh[in][0], bh[in][1]);
                    MMA16816(acc[im][in], ah[im], bl[in][0], bl[in][1]);
                    MMA16816(acc[im][in], al[im], bh[in][0], bh[in][1]);
                }
        }
        __syncthreads();
    }

    // ---- epilogue: row-side (anchors = row tile) ----
#pragma unroll
    for (int im = 0; im < 4; im++)
#pragma unroll
        for (int eh = 0; eh < 2; eh++) {
            int rloc = wm * 64 + im * 16 + (lane >> 2) + eh * 8;
            float sqr = s_sqr[rloc];
            int   labr = s_labr[rloc];
            float A = s_hp2r[rloc], B = s_hpBr[rloc];
            float mx = 0.f, mn = BIGD2;
#pragma unroll
            for (int in = 0; in < 4; in++)
#pragma unroll
                for (int ec = 0; ec < 2; ec++) {
                    int cloc = wn * 32 + in * 8 + (lane & 3) * 2 + ec;
                    float dot = acc[im][in][eh * 2 + ec];
                    float d2 = fmaxf(sqr + s_sqc[cloc] - 2.f * dot, 1e-12f);
                    if (labr != s_labc[cloc]) {
                        mx = fmaxf(mx, d2);
                        if (d2 > A && d2 < B) mn = fminf(mn, d2);
                    }
                }
            if (mx > 0.f) atomicMax(&shRmax[rloc], __float_as_uint(mx));
            if (mn < BIGD2) atomicMin(&shRmin[rloc], __float_as_uint(mn));
        }

    // ---- epilogue: col-side (anchors = col tile; symmetric distances) ----
#pragma unroll
    for (int in = 0; in < 4; in++)
#pragma unroll
        for (int ec = 0; ec < 2; ec++) {
            int cloc = wn * 32 + in * 8 + (lane & 3) * 2 + ec;
            float sqc = s_sqc[cloc];
            int   labc = s_labc[cloc];
            float A = s_hp2c[cloc], B = s_hpBc[cloc];
            float mx = 0.f, mn = BIGD2;
#pragma unroll
            for (int im = 0; im < 4; im++)
#pragma unroll
                for (int eh = 0; eh < 2; eh++) {
                    int rloc = wm * 64 + im * 16 + (lane >> 2) + eh * 8;
                    float dot = acc[im][in][eh * 2 + ec];
                    float d2 = fmaxf(s_sqr[rloc] + sqc - 2.f * dot, 1e-12f);
                    if (labc != s_labr[rloc]) {
                        mx = fmaxf(mx, d2);
                        if (d2 > A && d2 < B) mn = fminf(mn, d2);
                    }
                }
            if (mx > 0.f) atomicMax(&shCmax[cloc], __float_as_uint(mx));
            if (mn < BIGD2) atomicMin(&shCmin[cloc], __float_as_uint(mn));
        }

    __syncthreads();
    if (tid < 128) {
        if (shRmax[tid]) atomicMax(&g_hnfb[rowBase + tid], shRmax[tid]);
        if (shRmin[tid] != __float_as_uint(BIGD2)) {
            atomicMin(&g_hnsemi[rowBase + tid], shRmin[tid]);
            g_semiflag = 1;
        }
        if (shCmax[tid]) atomicMax(&g_hnfb[colBase + tid], shCmax[tid]);
        if (shCmin[tid] != __float_as_uint(BIGD2)) {
            atomicMin(&g_hnsemi[colBase + tid], shCmin[tid]);
            g_semiflag = 1;
        }
    }
}

__global__ void finalize_kernel(float* __restrict__ out, int n) {
    bool useSemi = (g_semiflag != 0);
    float sum = 0.f;
    int cnt = 0;
    for (int i = threadIdx.x; i < n; i += blockDim.x) {
        float hp = sqrtf(g_hp2[i]);
        unsigned hb = useSemi ? g_hnsemi[i] : g_hnfb[i];
        float hn = sqrtf(__uint_as_float(hb));
        float t = hp - hn + MARGIN;
        if (t < 0.f) t = 0.f;
        sum += t;
        if (t > 0.f) cnt++;
    }
    for (int o = 16; o; o >>= 1) {
        sum += __shfl_xor_sync(0xffffffffu, sum, o);
        cnt += __shfl_xor_sync(0xffffffffu, cnt, o);
    }
    __shared__ float wsum[32];
    __shared__ int wcnt[32];
    int lane = threadIdx.x & 31, w = threadIdx.x >> 5;
    if (lane == 0) { wsum[w] = sum; wcnt[w] = cnt; }
    __syncthreads();
    if (threadIdx.x == 0) {
        float s = 0.f; int c = 0;
        for (int k = 0; k < (int)(blockDim.x >> 5); k++) { s += wsum[k]; c += wcnt[k]; }
        out[0] = (c > 0) ? (s / (float)c) : 0.0f;
    }
}

// ---------------- launch ----------------
extern "C" void kernel_launch(void* const* d_in, const int* in_sizes, int n_in,
                              void* d_out, int out_size) {
    const float* E = (const float*)d_in[0];
    const int* labels = (const int*)d_in[1];
    int n = in_sizes[1];
    int d = in_sizes[0] / n;

    cudaFuncSetAttribute(gemm_kernel, cudaFuncAttributeMaxDynamicSharedMemorySize, SMEM_DYN);

    int initN = (n > NB ? n : NB);
    init_kernel<<<(initN + 255) / 256, 256>>>(n);
    convert_kernel<<<256, 256>>>(E, n * d);
    sq_kernel<<<n, 128>>>(E, d);
    hist_kernel<<<(n + 255) / 256, 256>>>(labels, n);
    scan_kernel<<<1, NB>>>();
    fill_kernel<<<(n + 255) / 256, 256>>>(labels, n);
    hp_kernel<<<n / 4, 128>>>(E, labels, n, d);
    int nb = n / 128;
    gemm_kernel<<<nb * (nb + 1) / 2, 256, SMEM_DYN>>>(labels, n, d);
    finalize_kernel<<<1, 1024>>>((float*)d_out, n);
}

// round 4
// speedup vs baseline: 7.4012x; 1.9148x over previous
#include <cuda_runtime.h>
#include <cuda_fp16.h>
#include <cstdint>
#include <math.h>

#define MAXN   4096
#define MAXD   512
#define NB     1024
#define MARGIN 0.3f
#define BIGD2  3.0e38f

// ---------------- scratch ----------------
__device__ __align__(16) __half g_Ehi[MAXN * MAXD];
__device__ __align__(16) __half g_Elo[MAXN * MAXD];
__device__ float    g_sq[MAXN];
__device__ float    g_hp2[MAXN];
__device__ float    g_hpB2[MAXN];
__device__ unsigned g_hnfb[MAXN];
__device__ unsigned g_hnsemi[MAXN];
__device__ int      g_semiflag;
__device__ int      g_ccount[NB];
__device__ int      g_coff[NB];
__device__ int      g_clist[MAXN];

__device__ __forceinline__ uint32_t smem_u32(const void* p) {
    uint32_t a;
    asm("{ .reg .u64 t; cvta.to.shared.u64 t, %1; cvt.u32.u64 %0, t; }" : "=r"(a) : "l"(p));
    return a;
}

#define CP_ASYNC16(dst, src) \
    asm volatile("cp.async.cg.shared.global [%0], [%1], 16;" :: "r"(dst), "l"(src))
#define CP_COMMIT() asm volatile("cp.async.commit_group;")
#define CP_WAIT2()  asm volatile("cp.async.wait_group 2;")
#define CP_WAIT1()  asm volatile("cp.async.wait_group 1;")
#define CP_WAIT0()  asm volatile("cp.async.wait_group 0;")

#define LDM4(r0, r1, r2, r3, addr)                                              \
    asm volatile("ldmatrix.sync.aligned.m8n8.x4.shared.b16 {%0,%1,%2,%3}, [%4];" \
        : "=r"(r0), "=r"(r1), "=r"(r2), "=r"(r3) : "r"(addr))

#define MMA16816(c, a, b0, b1)                                                   \
    asm volatile("mma.sync.aligned.m16n8k16.row.col.f32.f16.f16.f32 "            \
        "{%0,%1,%2,%3},{%4,%5,%6,%7},{%8,%9},{%0,%1,%2,%3};"                     \
        : "+f"((c)[0]), "+f"((c)[1]), "+f"((c)[2]), "+f"((c)[3])                 \
        : "r"((a)[0]), "r"((a)[1]), "r"((a)[2]), "r"((a)[3]), "r"(b0), "r"(b1))

// ---------------- kernel 0: convert + row sq + per-row init ----------------
__global__ void convsq_kernel(const float* __restrict__ E, int d) {
    int row = blockIdx.x;
    int t = threadIdx.x;               // 128 threads, d=512 -> 1 float4 each
    const float4* p = (const float4*)(E + (size_t)row * d);
    int d4 = d >> 2;
    float s = 0.f;
    for (int c = t; c < d4; c += blockDim.x) {
        float4 v = p[c];
        s += v.x * v.x + v.y * v.y + v.z * v.z + v.w * v.w;
        __half h0 = __float2half(v.x), h1 = __float2half(v.y);
        __half h2 = __float2half(v.z), h3 = __float2half(v.w);
        __half2 hi01 = __halves2half2(h0, h1), hi23 = __halves2half2(h2, h3);
        __half2 lo01 = __halves2half2(__float2half(v.x - __half2float(h0)),
                                      __float2half(v.y - __half2float(h1)));
        __half2 lo23 = __halves2half2(__float2half(v.z - __half2float(h2)),
                                      __float2half(v.w - __half2float(h3)));
        size_t o = (size_t)row * d + 4 * c;
        *(__half2*)(g_Ehi + o) = hi01; *(__half2*)(g_Ehi + o + 2) = hi23;
        *(__half2*)(g_Elo + o) = lo01; *(__half2*)(g_Elo + o + 2) = lo23;
    }
    for (int o = 16; o; o >>= 1) s += __shfl_xor_sync(0xffffffffu, s, o);
    __shared__ float ws[4];
    int lane = t & 31, w = t >> 5;
    if (lane == 0) ws[w] = s;
    __syncthreads();
    if (t == 0) {
        float tot = 0.f;
        for (int k = 0; k < (int)(blockDim.x >> 5); k++) tot += ws[k];
        g_sq[row] = tot;
        g_hnfb[row] = 0u;
        g_hnsemi[row] = __float_as_uint(BIGD2);
        if (row == 0) g_semiflag = 0;
    }
}

// ---------------- kernel 1: hist + scan + fill (single block) ----------------
__global__ void classlist_kernel(const int* __restrict__ labels, int n) {
    __shared__ int cnt[NB];
    __shared__ int s[NB];
    __shared__ int cur[NB];
    int t = threadIdx.x;               // 1024 threads
    cnt[t] = 0;
    __syncthreads();
    for (int i = t; i < n; i += blockDim.x) atomicAdd(&cnt[labels[i] & (NB - 1)], 1);
    __syncthreads();
    int v = cnt[t];
    s[t] = v;
    for (int off = 1; off < NB; off <<= 1) {
        __syncthreads();
        int u = (t >= off) ? s[t - off] : 0;
        __syncthreads();
        s[t] += u;
    }
    __syncthreads();
    int excl = s[t] - v;
    g_coff[t] = excl;
    g_ccount[t] = v;
    cur[t] = excl;
    __syncthreads();
    for (int i = t; i < n; i += blockDim.x) {
        int c = labels[i] & (NB - 1);
        int pos = atomicAdd(&cur[c], 1);
        g_clist[pos] = i;
    }
}

// ---------------- kernel 2: exact fp32 hardest positive (1 warp / anchor) ----------------
__global__ void hp_kernel(const float* __restrict__ E, const int* __restrict__ labels,
                          int n, int d) {
    int w = (blockIdx.x * blockDim.x + threadIdx.x) >> 5;
    int lid = threadIdx.x & 31;
    if (w >= n) return;
    int c = labels[w] & (NB - 1);
    const float4* ea = (const float4*)(E + (size_t)w * d);
    int dk4 = d >> 7;                  // float4's per lane (4 for d=512)
    float4 a0[MAXD / 128];
#pragma unroll
    for (int j = 0; j < MAXD / 128; j++) if (j < dk4) a0[j] = ea[lid + 32 * j];
    int beg = g_coff[c], cnt = g_ccount[c];
    float sqa = g_sq[w];
    float maxd2 = 0.f;
    for (int t = 0; t < cnt; t++) {
        int m = g_clist[beg + t];
        const float4* em = (const float4*)(E + (size_t)m * d);
        float dot = 0.f;
#pragma unroll
        for (int j = 0; j < MAXD / 128; j++)
            if (j < dk4) {
                float4 b = em[lid + 32 * j];
                dot += a0[j].x * b.x + a0[j].y * b.y + a0[j].z * b.z + a0[j].w * b.w;
            }
        for (int o = 16; o; o >>= 1) dot += __shfl_xor_sync(0xffffffffu, dot, o);
        float d2 = sqa + g_sq[m] - 2.f * dot;
        maxd2 = fmaxf(maxd2, d2);
    }
    if (lid == 0) {
        float h2 = fmaxf(maxd2, 1e-12f);
        g_hp2[w] = h2;
        float hp = sqrtf(h2);
        g_hpB2[w] = (hp + MARGIN) * (hp + MARGIN);
    }
}

// ---------------- kernel 3: HMMA GEMM (triangle), swizzled smem, 3-stage pipeline ----------------
#define BK      32                    // halves per k-chunk (64 bytes)
#define TILEB   8192                  // 128 rows * 64 B
#define STAGEB  (4 * TILEB)           // Ahi, Alo, Bhi, Blo = 32 KB
#define AUXO    (3 * STAGEB)          // 98304
#define SMEM_DYN (AUXO + 6144)

__global__ __launch_bounds__(256, 1) void gemm_kernel(const int* __restrict__ labels,
                                                      int n, int d) {
    extern __shared__ char sm[];
    uint32_t sb = smem_u32(sm);
    int tid = threadIdx.x, lane = tid & 31, wid = tid >> 5;
    int wm = wid >> 2, wn = wid & 3;

    // triangle mapping: bid -> (by, bx), bx <= by
    int bid = blockIdx.x;
    int by = (int)((sqrtf(8.f * (float)bid + 1.f) - 1.f) * 0.5f);
    while ((by + 1) * (by + 2) / 2 <= bid) by++;
    while (by * (by + 1) / 2 > bid) by--;
    int bx = bid - by * (by + 1) / 2;
    int rowBase = by * 128, colBase = bx * 128;

    float*    s_sqc  = (float*)(sm + AUXO);
    int*      s_labc = (int*)(sm + AUXO + 512);
    float*    s_sqr  = (float*)(sm + AUXO + 1024);
    int*      s_labr = (int*)(sm + AUXO + 1536);
    float*    s_hp2r = (float*)(sm + AUXO + 2048);
    float*    s_hpBr = (float*)(sm + AUXO + 2560);
    float*    s_hp2c = (float*)(sm + AUXO + 3072);
    float*    s_hpBc = (float*)(sm + AUXO + 3584);
    unsigned* shRmax = (unsigned*)(sm + AUXO + 4096);
    unsigned* shRmin = (unsigned*)(sm + AUXO + 4608);
    unsigned* shCmax = (unsigned*)(sm + AUXO + 5120);
    unsigned* shCmin = (unsigned*)(sm + AUXO + 5632);

    if (tid < 128) {
        s_sqc[tid]  = g_sq[colBase + tid];  s_labc[tid] = labels[colBase + tid];
        s_sqr[tid]  = g_sq[rowBase + tid];  s_labr[tid] = labels[rowBase + tid];
        s_hp2r[tid] = g_hp2[rowBase + tid]; s_hpBr[tid] = g_hpB2[rowBase + tid];
        s_hp2c[tid] = g_hp2[colBase + tid]; s_hpBc[tid] = g_hpB2[colBase + tid];
        shRmax[tid] = 0u; shRmin[tid] = __float_as_uint(BIGD2);
        shCmax[tid] = 0u; shCmin[tid] = __float_as_uint(BIGD2);
    }

    // cp.async slots: 8 x 16B per thread per stage (2048 chunks / 256 threads)
    const __half* gsrc[8];
    uint32_t sdst[8];
    {
        const __half* tps[4] = {g_Ehi + (size_t)rowBase * d, g_Elo + (size_t)rowBase * d,
                                g_Ehi + (size_t)colBase * d, g_Elo + (size_t)colBase * d};
#pragma unroll
        for (int t = 0; t < 8; t++) {
            int tile = t >> 1;
            int w = ((t & 1) << 8) + tid;           // 0..511
            int r = w >> 2, ch = w & 3;
            gsrc[t] = tps[tile] + (size_t)r * d + ch * 8;
            sdst[t] = sb + tile * TILEB + r * 64 + (((ch + (r >> 1)) & 3) << 4);
        }
    }

    // per-lane swizzled ldmatrix addresses (invariant across im/p strides of 16 rows)
    int r0A = wm * 64 + (lane & 15);
    int cA  = lane >> 4;
    uint32_t aoff0 = (uint32_t)(r0A * 64 + (((cA + (r0A >> 1)) & 3) << 4));
    uint32_t aoff1 = (uint32_t)(r0A * 64 + (((cA + 2 + (r0A >> 1)) & 3) << 4));
    int r0B = wn * 32 + (lane & 7) + ((lane >> 4) & 1) * 8;
    int cB  = (lane >> 3) & 1;
    uint32_t boff0 = (uint32_t)(r0B * 64 + (((cB + (r0B >> 1)) & 3) << 4));
    uint32_t boff1 = (uint32_t)(r0B * 64 + (((cB + 2 + (r0B >> 1)) & 3) << 4));

    float acc[4][4][4];
#pragma unroll
    for (int im = 0; im < 4; im++)
#pragma unroll
        for (int in = 0; in < 4; in++)
#pragma unroll
            for (int e = 0; e < 4; e++) acc[im][in][e] = 0.f;

    int NC = d / BK;   // 16

    // prologue: stages 0 and 1
#pragma unroll
    for (int t = 0; t < 8; t++) CP_ASYNC16(sdst[t], gsrc[t]);
    CP_COMMIT();
#pragma unroll
    for (int t = 0; t < 8; t++) CP_ASYNC16(sdst[t] + STAGEB, gsrc[t] + BK);
    CP_COMMIT();

    int cb = 0, ib = 2;
    for (int c = 0; c < NC; c++) {
        if (c + 2 < NC) {
            int k0 = (c + 2) * BK;
            uint32_t so = (uint32_t)ib * STAGEB;
#pragma unroll
            for (int t = 0; t < 8; t++) CP_ASYNC16(sdst[t] + so, gsrc[t] + k0);
            CP_COMMIT();
            CP_WAIT2();
            ib = (ib == 2) ? 0 : ib + 1;
        } else if (c + 1 < NC) {
            CP_WAIT1();
        } else {
            CP_WAIT0();
        }
        __syncthreads();

        uint32_t base = sb + (uint32_t)cb * STAGEB;
#pragma unroll
        for (int k16 = 0; k16 < 2; k16++) {
            uint32_t ao = k16 ? aoff1 : aoff0;
            uint32_t bo = k16 ? boff1 : boff0;
            uint32_t ah[4][4], al[4][4], bh[4][2], bl[4][2];
#pragma unroll
            for (int im = 0; im < 4; im++) {
                uint32_t aA = base + im * 1024 + ao;
                LDM4(ah[im][0], ah[im][1], ah[im][2], ah[im][3], aA);
                LDM4(al[im][0], al[im][1], al[im][2], al[im][3], aA + TILEB);
            }
#pragma unroll
            for (int p = 0; p < 2; p++) {
                uint32_t aB = base + 2 * TILEB + p * 1024 + bo;
                LDM4(bh[2 * p][0], bh[2 * p][1], bh[2 * p + 1][0], bh[2 * p + 1][1], aB);
                LDM4(bl[2 * p][0], bl[2 * p][1], bl[2 * p + 1][0], bl[2 * p + 1][1], aB + TILEB);
            }
#pragma unroll
            for (int im = 0; im < 4; im++)
#pragma unroll
                for (int in = 0; in < 4; in++) {
                    MMA16816(acc[im][in], ah[im], bh[in][0], bh[in][1]);
                    MMA16816(acc[im][in], ah[im], bl[in][0], bl[in][1]);
                    MMA16816(acc[im][in], al[im], bh[in][0], bh[in][1]);
                }
        }
        __syncthreads();
        cb = (cb == 2) ? 0 : cb + 1;
    }

    // ---- epilogue: row-side ----
#pragma unroll
    for (int im = 0; im < 4; im++)
#pragma unroll
        for (int eh = 0; eh < 2; eh++) {
            int rloc = wm * 64 + im * 16 + (lane >> 2) + eh * 8;
            float sqr = s_sqr[rloc];
            int   labr = s_labr[rloc];
            float A = s_hp2r[rloc], B = s_hpBr[rloc];
            float mx = 0.f, mn = BIGD2;
#pragma unroll
            for (int in = 0; in < 4; in++)
#pragma unroll
                for (int ec = 0; ec < 2; ec++) {
                    int cloc = wn * 32 + in * 8 + (lane & 3) * 2 + ec;
                    float dot = acc[im][in][eh * 2 + ec];
                    float d2 = fmaxf(sqr + s_sqc[cloc] - 2.f * dot, 1e-12f);
                    if (labr != s_labc[cloc]) {
                        mx = fmaxf(mx, d2);
                        if (d2 > A && d2 < B) mn = fminf(mn, d2);
                    }
                }
            if (mx > 0.f) atomicMax(&shRmax[rloc], __float_as_uint(mx));
            if (mn < BIGD2) atomicMin(&shRmin[rloc], __float_as_uint(mn));
        }

    // ---- epilogue: col-side (symmetric) ----
#pragma unroll
    for (int in = 0; in < 4; in++)
#pragma unroll
        for (int ec = 0; ec < 2; ec++) {
            int cloc = wn * 32 + in * 8 + (lane & 3) * 2 + ec;
            float sqc = s_sqc[cloc];
            int   labc = s_labc[cloc];
            float A = s_hp2c[cloc], B = s_hpBc[cloc];
            float mx = 0.f, mn = BIGD2;
#pragma unroll
            for (int im = 0; im < 4; im++)
#pragma unroll
                for (int eh = 0; eh < 2; eh++) {
                    int rloc = wm * 64 + im * 16 + (lane >> 2) + eh * 8;
                    float dot = acc[im][in][eh * 2 + ec];
                    float d2 = fmaxf(s_sqr[rloc] + sqc - 2.f * dot, 1e-12f);
                    if (labc != s_labr[rloc]) {
                        mx = fmaxf(mx, d2);
                        if (d2 > A && d2 < B) mn = fminf(mn, d2);
                    }
                }
            if (mx > 0.f) atomicMax(&shCmax[cloc], __float_as_uint(mx));
            if (mn < BIGD2) atomicMin(&shCmin[cloc], __float_as_uint(mn));
        }

    __syncthreads();
    if (tid < 128) {
        if (shRmax[tid]) atomicMax(&g_hnfb[rowBase + tid], shRmax[tid]);
        if (shRmin[tid] != __float_as_uint(BIGD2)) {
            atomicMin(&g_hnsemi[rowBase + tid], shRmin[tid]);
            g_semiflag = 1;
        }
        if (shCmax[tid]) atomicMax(&g_hnfb[colBase + tid], shCmax[tid]);
        if (shCmin[tid] != __float_as_uint(BIGD2)) {
            atomicMin(&g_hnsemi[colBase + tid], shCmin[tid]);
            g_semiflag = 1;
        }
    }
}

// ---------------- kernel 4: finalize ----------------
__global__ void finalize_kernel(float* __restrict__ out, int n) {
    bool useSemi = (g_semiflag != 0);
    float sum = 0.f;
    int cnt = 0;
    for (int i = threadIdx.x; i < n; i += blockDim.x) {
        float hp = sqrtf(g_hp2[i]);
        unsigned hb = useSemi ? g_hnsemi[i] : g_hnfb[i];
        float hn = sqrtf(__uint_as_float(hb));
        float t = hp - hn + MARGIN;
        if (t < 0.f) t = 0.f;
        sum += t;
        if (t > 0.f) cnt++;
    }
    for (int o = 16; o; o >>= 1) {
        sum += __shfl_xor_sync(0xffffffffu, sum, o);
        cnt += __shfl_xor_sync(0xffffffffu, cnt, o);
    }
    __shared__ float wsum[32];
    __shared__ int wcnt[32];
    int lane = threadIdx.x & 31, w = threadIdx.x >> 5;
    if (lane == 0) { wsum[w] = sum; wcnt[w] = cnt; }
    __syncthreads();
    if (threadIdx.x == 0) {
        float s = 0.f; int c = 0;
        for (int k = 0; k < (int)(blockDim.x >> 5); k++) { s += wsum[k]; c += wcnt[k]; }
        out[0] = (c > 0) ? (s / (float)c) : 0.0f;
    }
}

// ---------------- launch ----------------
extern "C" void kernel_launch(void* const* d_in, const int* in_sizes, int n_in,
                              void* d_out, int out_size) {
    const float* E = (const float*)d_in[0];
    const int* labels = (const int*)d_in[1];
    int n = in_sizes[1];
    int d = in_sizes[0] / n;

    cudaFuncSetAttribute(gemm_kernel, cudaFuncAttributeMaxDynamicSharedMemorySize, SMEM_DYN);

    convsq_kernel<<<n, 128>>>(E, d);                       // launch 0
    classlist_kernel<<<1, NB>>>(labels, n);                // launch 1
    hp_kernel<<<n / 4, 128>>>(E, labels, n, d);            // launch 2
    int nb = n / 128;
    gemm_kernel<<<nb * (nb + 1) / 2, 256, SMEM_DYN>>>(labels, n, d);  // launch 3 (profiled)
    finalize_kernel<<<1, 1024>>>((float*)d_out, n);        // launch 4
}

// round 5
// speedup vs baseline: 7.5144x; 1.0153x over previous
#include <cuda_runtime.h>
#include <cuda_fp16.h>
#include <cstdint>
#include <math.h>

#define MAXN   4096
#define MAXD   512
#define NB     1024
#define MARGIN 0.3f
#define BIGD2  3.0e38f

// ---------------- scratch ----------------
__device__ __align__(16) __half g_Ehi[MAXN * MAXD];
__device__ __align__(16) __half g_Elo[MAXN * MAXD];
__device__ float    g_sq[MAXN];
__device__ float    g_hp2[MAXN];
__device__ float    g_hpB2[MAXN];
__device__ unsigned g_hnfb[MAXN];
__device__ unsigned g_hnsemi[MAXN];
__device__ int      g_semiflag;
__device__ int      g_ccount[NB];
__device__ int      g_coff[NB];
__device__ int      g_clist[MAXN];

__device__ __forceinline__ uint32_t smem_u32(const void* p) {
    uint32_t a;
    asm("{ .reg .u64 t; cvta.to.shared.u64 t, %1; cvt.u32.u64 %0, t; }" : "=r"(a) : "l"(p));
    return a;
}

#define CP_ASYNC16(dst, src) \
    asm volatile("cp.async.cg.shared.global [%0], [%1], 16;" :: "r"(dst), "l"(src))
#define CP_COMMIT() asm volatile("cp.async.commit_group;")
#define CP_WAIT2()  asm volatile("cp.async.wait_group 2;")
#define CP_WAIT1()  asm volatile("cp.async.wait_group 1;")
#define CP_WAIT0()  asm volatile("cp.async.wait_group 0;")

#define LDM4(r0, r1, r2, r3, addr)                                              \
    asm volatile("ldmatrix.sync.aligned.m8n8.x4.shared.b16 {%0,%1,%2,%3}, [%4];" \
        : "=r"(r0), "=r"(r1), "=r"(r2), "=r"(r3) : "r"(addr))

#define MMA16816(c, a, b0, b1)                                                   \
    asm volatile("mma.sync.aligned.m16n8k16.row.col.f32.f16.f16.f32 "            \
        "{%0,%1,%2,%3},{%4,%5,%6,%7},{%8,%9},{%0,%1,%2,%3};"                     \
        : "+f"((c)[0]), "+f"((c)[1]), "+f"((c)[2]), "+f"((c)[3])                 \
        : "r"((a)[0]), "r"((a)[1]), "r"((a)[2]), "r"((a)[3]), "r"(b0), "r"(b1))

// ---------------- kernel 0: convert + row sq + per-row init ----------------
__global__ void convsq_kernel(const float* __restrict__ E, int d) {
    int row = blockIdx.x;
    int t = threadIdx.x;
    const float4* p = (const float4*)(E + (size_t)row * d);
    int d4 = d >> 2;
    float s = 0.f;
    for (int c = t; c < d4; c += blockDim.x) {
        float4 v = p[c];
        s += v.x * v.x + v.y * v.y + v.z * v.z + v.w * v.w;
        __half h0 = __float2half(v.x), h1 = __float2half(v.y);
        __half h2 = __float2half(v.z), h3 = __float2half(v.w);
        __half2 hi01 = __halves2half2(h0, h1), hi23 = __halves2half2(h2, h3);
        __half2 lo01 = __halves2half2(__float2half(v.x - __half2float(h0)),
                                      __float2half(v.y - __half2float(h1)));
        __half2 lo23 = __halves2half2(__float2half(v.z - __half2float(h2)),
                                      __float2half(v.w - __half2float(h3)));
        size_t o = (size_t)row * d + 4 * c;
        *(__half2*)(g_Ehi + o) = hi01; *(__half2*)(g_Ehi + o + 2) = hi23;
        *(__half2*)(g_Elo + o) = lo01; *(__half2*)(g_Elo + o + 2) = lo23;
    }
    for (int o = 16; o; o >>= 1) s += __shfl_xor_sync(0xffffffffu, s, o);
    __shared__ float ws[4];
    int lane = t & 31, w = t >> 5;
    if (lane == 0) ws[w] = s;
    __syncthreads();
    if (t == 0) {
        float tot = 0.f;
        for (int k = 0; k < (int)(blockDim.x >> 5); k++) tot += ws[k];
        g_sq[row] = tot;
        g_hnfb[row] = 0u;
        g_hnsemi[row] = __float_as_uint(BIGD2);
        if (row == 0) g_semiflag = 0;
    }
}

// ---------------- kernel 1: hist + scan + fill (single block) ----------------
__global__ void classlist_kernel(const int* __restrict__ labels, int n) {
    __shared__ int cnt[NB];
    __shared__ int s[NB];
    __shared__ int cur[NB];
    int t = threadIdx.x;
    cnt[t] = 0;
    __syncthreads();
    for (int i = t; i < n; i += blockDim.x) atomicAdd(&cnt[labels[i] & (NB - 1)], 1);
    __syncthreads();
    int v = cnt[t];
    s[t] = v;
    for (int off = 1; off < NB; off <<= 1) {
        __syncthreads();
        int u = (t >= off) ? s[t - off] : 0;
        __syncthreads();
        s[t] += u;
    }
    __syncthreads();
    int excl = s[t] - v;
    g_coff[t] = excl;
    g_ccount[t] = v;
    cur[t] = excl;
    __syncthreads();
    for (int i = t; i < n; i += blockDim.x) {
        int c = labels[i] & (NB - 1);
        int pos = atomicAdd(&cur[c], 1);
        g_clist[pos] = i;
    }
}

// ---------------- kernel 2: exact fp32 hardest positive (1 warp / anchor) ----------------
__global__ void hp_kernel(const float* __restrict__ E, const int* __restrict__ labels,
                          int n, int d) {
    int w = (blockIdx.x * blockDim.x + threadIdx.x) >> 5;
    int lid = threadIdx.x & 31;
    if (w >= n) return;
    int c = labels[w] & (NB - 1);
    const float4* ea = (const float4*)(E + (size_t)w * d);
    int dk4 = d >> 7;
    float4 a0[MAXD / 128];
#pragma unroll
    for (int j = 0; j < MAXD / 128; j++) if (j < dk4) a0[j] = ea[lid + 32 * j];
    int beg = g_coff[c], cnt = g_ccount[c];
    float sqa = g_sq[w];
    float maxd2 = 0.f;
    for (int t = 0; t < cnt; t++) {
        int m = g_clist[beg + t];
        const float4* em = (const float4*)(E + (size_t)m * d);
        float dot = 0.f;
#pragma unroll
        for (int j = 0; j < MAXD / 128; j++)
            if (j < dk4) {
                float4 b = em[lid + 32 * j];
                dot += a0[j].x * b.x + a0[j].y * b.y + a0[j].z * b.z + a0[j].w * b.w;
            }
        for (int o = 16; o; o >>= 1) dot += __shfl_xor_sync(0xffffffffu, dot, o);
        float d2 = sqa + g_sq[m] - 2.f * dot;
        maxd2 = fmaxf(maxd2, d2);
    }
    if (lid == 0) {
        float h2 = fmaxf(maxd2, 1e-12f);
        g_hp2[w] = h2;
        float hp = sqrtf(h2);
        g_hpB2[w] = (hp + MARGIN) * (hp + MARGIN);
    }
}

// ---------------- kernel 3: HMMA GEMM, 512 threads / 16 warps, 3-stage pipeline ----------------
#define BK      32                    // halves per k-chunk (64 bytes)
#define TILEB   8192                  // 128 rows * 64 B
#define STAGEB  (4 * TILEB)           // Ahi, Alo, Bhi, Blo = 32 KB
#define AUXO    (3 * STAGEB)          // 98304
#define SMEM_DYN (AUXO + 6144)

__global__ __launch_bounds__(512, 1) void gemm_kernel(const int* __restrict__ labels,
                                                      int n, int d) {
    extern __shared__ char sm[];
    uint32_t sb = smem_u32(sm);
    int tid = threadIdx.x, lane = tid & 31, wid = tid >> 5;
    int wm = wid >> 2, wn = wid & 3;   // 4x4 warp grid; warp tile 32x32

    // triangle mapping: bid -> (by, bx), bx <= by
    int bid = blockIdx.x;
    int by = (int)((sqrtf(8.f * (float)bid + 1.f) - 1.f) * 0.5f);
    while ((by + 1) * (by + 2) / 2 <= bid) by++;
    while (by * (by + 1) / 2 > bid) by--;
    int bx = bid - by * (by + 1) / 2;
    int rowBase = by * 128, colBase = bx * 128;

    float*    s_sqc  = (float*)(sm + AUXO);
    int*      s_labc = (int*)(sm + AUXO + 512);
    float*    s_sqr  = (float*)(sm + AUXO + 1024);
    int*      s_labr = (int*)(sm + AUXO + 1536);
    float*    s_hp2r = (float*)(sm + AUXO + 2048);
    float*    s_hpBr = (float*)(sm + AUXO + 2560);
    float*    s_hp2c = (float*)(sm + AUXO + 3072);
    float*    s_hpBc = (float*)(sm + AUXO + 3584);
    unsigned* shRmax = (unsigned*)(sm + AUXO + 4096);
    unsigned* shRmin = (unsigned*)(sm + AUXO + 4608);
    unsigned* shCmax = (unsigned*)(sm + AUXO + 5120);
    unsigned* shCmin = (unsigned*)(sm + AUXO + 5632);

    if (tid < 128) {
        s_sqc[tid]  = g_sq[colBase + tid];  s_labc[tid] = labels[colBase + tid];
        s_sqr[tid]  = g_sq[rowBase + tid];  s_labr[tid] = labels[rowBase + tid];
        s_hp2r[tid] = g_hp2[rowBase + tid]; s_hpBr[tid] = g_hpB2[rowBase + tid];
        s_hp2c[tid] = g_hp2[colBase + tid]; s_hpBc[tid] = g_hpB2[colBase + tid];
        shRmax[tid] = 0u; shRmin[tid] = __float_as_uint(BIGD2);
        shCmax[tid] = 0u; shCmin[tid] = __float_as_uint(BIGD2);
    }

    // cp.async: 2048 16B chunks per stage / 512 threads = 4 per thread (1 per tile)
    const __half* gsrc[4];
    uint32_t sdst[4];
    {
        const __half* tps[4] = {g_Ehi + (size_t)rowBase * d, g_Elo + (size_t)rowBase * d,
                                g_Ehi + (size_t)colBase * d, g_Elo + (size_t)colBase * d};
        int r = tid >> 2, ch = tid & 3;
#pragma unroll
        for (int t = 0; t < 4; t++) {
            gsrc[t] = tps[t] + (size_t)r * d + ch * 8;
            sdst[t] = sb + t * TILEB + r * 64 + (((ch + (r >> 1)) & 3) << 4);
        }
    }

    // per-lane swizzled ldmatrix addresses
    int r0A = wm * 32 + (lane & 15);
    int cA  = lane >> 4;
    uint32_t aoff0 = (uint32_t)(r0A * 64 + (((cA + (r0A >> 1)) & 3) << 4));
    uint32_t aoff1 = (uint32_t)(r0A * 64 + (((cA + 2 + (r0A >> 1)) & 3) << 4));
    int r0B = wn * 32 + (lane & 7) + ((lane >> 4) & 1) * 8;
    int cB  = (lane >> 3) & 1;
    uint32_t boff0 = (uint32_t)(r0B * 64 + (((cB + (r0B >> 1)) & 3) << 4));
    uint32_t boff1 = (uint32_t)(r0B * 64 + (((cB + 2 + (r0B >> 1)) & 3) << 4));

    float acc[2][4][4];
#pragma unroll
    for (int im = 0; im < 2; im++)
#pragma unroll
        for (int in = 0; in < 4; in++)
#pragma unroll
            for (int e = 0; e < 4; e++) acc[im][in][e] = 0.f;

    int NC = d / BK;   // 16

    // prologue: stages 0 and 1
#pragma unroll
    for (int t = 0; t < 4; t++) CP_ASYNC16(sdst[t], gsrc[t]);
    CP_COMMIT();
#pragma unroll
    for (int t = 0; t < 4; t++) CP_ASYNC16(sdst[t] + STAGEB, gsrc[t] + BK);
    CP_COMMIT();

    int cb = 0, ib = 2;
    for (int c = 0; c < NC; c++) {
        if (c + 2 < NC) {
            int k0 = (c + 2) * BK;
            uint32_t so = (uint32_t)ib * STAGEB;
#pragma unroll
            for (int t = 0; t < 4; t++) CP_ASYNC16(sdst[t] + so, gsrc[t] + k0);
            CP_COMMIT();
            CP_WAIT2();
            ib = (ib == 2) ? 0 : ib + 1;
        } else if (c + 1 < NC) {
            CP_WAIT1();
        } else {
            CP_WAIT0();
        }
        __syncthreads();

        uint32_t base = sb + (uint32_t)cb * STAGEB;
#pragma unroll
        for (int k16 = 0; k16 < 2; k16++) {
            uint32_t ao = k16 ? aoff1 : aoff0;
            uint32_t bo = k16 ? boff1 : boff0;
            uint32_t ah[2][4], al[2][4], bh[4][2], bl[4][2];
#pragma unroll
            for (int im = 0; im < 2; im++) {
                uint32_t aA = base + im * 1024 + ao;
                LDM4(ah[im][0], ah[im][1], ah[im][2], ah[im][3], aA);
                LDM4(al[im][0], al[im][1], al[im][2], al[im][3], aA + TILEB);
            }
#pragma unroll
            for (int p = 0; p < 2; p++) {
                uint32_t aB = base + 2 * TILEB + p * 1024 + bo;
                LDM4(bh[2 * p][0], bh[2 * p][1], bh[2 * p + 1][0], bh[2 * p + 1][1], aB);
                LDM4(bl[2 * p][0], bl[2 * p][1], bl[2 * p + 1][0], bl[2 * p + 1][1], aB + TILEB);
            }
#pragma unroll
            for (int im = 0; im < 2; im++)
#pragma unroll
                for (int in = 0; in < 4; in++) {
                    MMA16816(acc[im][in], ah[im], bh[in][0], bh[in][1]);
                    MMA16816(acc[im][in], ah[im], bl[in][0], bl[in][1]);
                    MMA16816(acc[im][in], al[im], bh[in][0], bh[in][1]);
                }
        }
        __syncthreads();
        cb = (cb == 2) ? 0 : cb + 1;
    }

    // ---- epilogue: row-side ----
#pragma unroll
    for (int im = 0; im < 2; im++)
#pragma unroll
        for (int eh = 0; eh < 2; eh++) {
            int rloc = wm * 32 + im * 16 + (lane >> 2) + eh * 8;
            float sqr = s_sqr[rloc];
            int   labr = s_labr[rloc];
            float A = s_hp2r[rloc], B = s_hpBr[rloc];
            float mx = 0.f, mn = BIGD2;
#pragma unroll
            for (int in = 0; in < 4; in++)
#pragma unroll
                for (int ec = 0; ec < 2; ec++) {
                    int cloc = wn * 32 + in * 8 + (lane & 3) * 2 + ec;
                    float dot = acc[im][in][eh * 2 + ec];
                    float d2 = fmaxf(sqr + s_sqc[cloc] - 2.f * dot, 1e-12f);
                    if (labr != s_labc[cloc]) {
                        mx = fmaxf(mx, d2);
                        if (d2 > A && d2 < B) mn = fminf(mn, d2);
                    }
                }
            if (mx > 0.f) atomicMax(&shRmax[rloc], __float_as_uint(mx));
            if (mn < BIGD2) atomicMin(&shRmin[rloc], __float_as_uint(mn));
        }

    // ---- epilogue: col-side (symmetric) ----
#pragma unroll
    for (int in = 0; in < 4; in++)
#pragma unroll
        for (int ec = 0; ec < 2; ec++) {
            int cloc = wn * 32 + in * 8 + (lane & 3) * 2 + ec;
            float sqc = s_sqc[cloc];
            int   labc = s_labc[cloc];
            float A = s_hp2c[cloc], B = s_hpBc[cloc];
            float mx = 0.f, mn = BIGD2;
#pragma unroll
            for (int im = 0; im < 2; im++)
#pragma unroll
                for (int eh = 0; eh < 2; eh++) {
                    int rloc = wm * 32 + im * 16 + (lane >> 2) + eh * 8;
                    float dot = acc[im][in][eh * 2 + ec];
                    float d2 = fmaxf(s_sqr[rloc] + sqc - 2.f * dot, 1e-12f);
                    if (labc != s_labr[rloc]) {
                        mx = fmaxf(mx, d2);
                        if (d2 > A && d2 < B) mn = fminf(mn, d2);
                    }
                }
            if (mx > 0.f) atomicMax(&shCmax[cloc], __float_as_uint(mx));
            if (mn < BIGD2) atomicMin(&shCmin[cloc], __float_as_uint(mn));
        }

    __syncthreads();
    if (tid < 128) {
        if (shRmax[tid]) atomicMax(&g_hnfb[rowBase + tid], shRmax[tid]);
        if (shRmin[tid] != __float_as_uint(BIGD2)) {
            atomicMin(&g_hnsemi[rowBase + tid], shRmin[tid]);
            g_semiflag = 1;
        }
        if (shCmax[tid]) atomicMax(&g_hnfb[colBase + tid], shCmax[tid]);
        if (shCmin[tid] != __float_as_uint(BIGD2)) {
            atomicMin(&g_hnsemi[colBase + tid], shCmin[tid]);
            g_semiflag = 1;
        }
    }
}

// ---------------- kernel 4: finalize ----------------
__global__ void finalize_kernel(float* __restrict__ out, int n) {
    bool useSemi = (g_semiflag != 0);
    float sum = 0.f;
    int cnt = 0;
    for (int i = threadIdx.x; i < n; i += blockDim.x) {
        float hp = sqrtf(g_hp2[i]);
        unsigned hb = useSemi ? g_hnsemi[i] : g_hnfb[i];
        float hn = sqrtf(__uint_as_float(hb));
        float t = hp - hn + MARGIN;
        if (t < 0.f) t = 0.f;
        sum += t;
        if (t > 0.f) cnt++;
    }
    for (int o = 16; o; o >>= 1) {
        sum += __shfl_xor_sync(0xffffffffu, sum, o);
        cnt += __shfl_xor_sync(0xffffffffu, cnt, o);
    }
    __shared__ float wsum[32];
    __shared__ int wcnt[32];
    int lane = threadIdx.x & 31, w = threadIdx.x >> 5;
    if (lane == 0) { wsum[w] = sum; wcnt[w] = cnt; }
    __syncthreads();
    if (threadIdx.x == 0) {
        float s = 0.f; int c = 0;
        for (int k = 0; k < (int)(blockDim.x >> 5); k++) { s += wsum[k]; c += wcnt[k]; }
        out[0] = (c > 0) ? (s / (float)c) : 0.0f;
    }
}

// ---------------- launch ----------------
extern "C" void kernel_launch(void* const* d_in, const int* in_sizes, int n_in,
                              void* d_out, int out_size) {
    const float* E = (const float*)d_in[0];
    const int* labels = (const int*)d_in[1];
    int n = in_sizes[1];
    int d = in_sizes[0] / n;

    cudaFuncSetAttribute(gemm_kernel, cudaFuncAttributeMaxDynamicSharedMemorySize, SMEM_DYN);

    convsq_kernel<<<n, 128>>>(E, d);                       // launch 0
    classlist_kernel<<<1, NB>>>(labels, n);                // launch 1
    hp_kernel<<<n / 4, 128>>>(E, labels, n, d);            // launch 2
    int nb = n / 128;
    gemm_kernel<<<nb * (nb + 1) / 2, 512, SMEM_DYN>>>(labels, n, d);  // launch 3 (profiled)
    finalize_kernel<<<1, 1024>>>((float*)d_out, n);        // launch 4
}

// round 6
// speedup vs baseline: 9.1761x; 1.2211x over previous
#include <cuda_runtime.h>
#include <cuda_fp16.h>
#include <cstdint>
#include <math.h>

#define MAXN   4096
#define MAXD   512
#define NB     1024
#define MARGIN 0.3f
#define BIGD2  3.0e38f

// ---------------- scratch ----------------
__device__ __align__(16) __half g_Ehi[MAXN * MAXD];
__device__ __align__(16) __half g_Elo[MAXN * MAXD];
__device__ float    g_sq[MAXN];
__device__ float    g_hp2[MAXN];
__device__ float    g_hpB2[MAXN];
__device__ unsigned g_hnfb[MAXN];
__device__ unsigned g_hnsemi[MAXN];
__device__ int      g_semiflag;
__device__ int      g_ccount[NB];
__device__ int      g_coff[NB];
__device__ int      g_clist[MAXN];

__device__ __forceinline__ uint32_t smem_u32(const void* p) {
    uint32_t a;
    asm("{ .reg .u64 t; cvta.to.shared.u64 t, %1; cvt.u32.u64 %0, t; }" : "=r"(a) : "l"(p));
    return a;
}

#define CP_ASYNC16(dst, src) \
    asm volatile("cp.async.cg.shared.global [%0], [%1], 16;" :: "r"(dst), "l"(src))
#define CP_COMMIT() asm volatile("cp.async.commit_group;")
#define CP_WAIT1()  asm volatile("cp.async.wait_group 1;")
#define CP_WAIT0()  asm volatile("cp.async.wait_group 0;")

#define LDM4(r0, r1, r2, r3, addr)                                              \
    asm volatile("ldmatrix.sync.aligned.m8n8.x4.shared.b16 {%0,%1,%2,%3}, [%4];" \
        : "=r"(r0), "=r"(r1), "=r"(r2), "=r"(r3) : "r"(addr))

#define MMA16816(c, a, b0, b1)                                                   \
    asm volatile("mma.sync.aligned.m16n8k16.row.col.f32.f16.f16.f32 "            \
        "{%0,%1,%2,%3},{%4,%5,%6,%7},{%8,%9},{%0,%1,%2,%3};"                     \
        : "+f"((c)[0]), "+f"((c)[1]), "+f"((c)[2]), "+f"((c)[3])                 \
        : "r"((a)[0]), "r"((a)[1]), "r"((a)[2]), "r"((a)[3]), "r"(b0), "r"(b1))

// ---------------- kernel 0: convert + row sq + per-row init ----------------
__global__ void convsq_kernel(const float* __restrict__ E, int d) {
    int row = blockIdx.x;
    int t = threadIdx.x;
    const float4* p = (const float4*)(E + (size_t)row * d);
    int d4 = d >> 2;
    float s = 0.f;
    for (int c = t; c < d4; c += blockDim.x) {
        float4 v = p[c];
        s += v.x * v.x + v.y * v.y + v.z * v.z + v.w * v.w;
        __half h0 = __float2half(v.x), h1 = __float2half(v.y);
        __half h2 = __float2half(v.z), h3 = __float2half(v.w);
        __half2 hi01 = __halves2half2(h0, h1), hi23 = __halves2half2(h2, h3);
        __half2 lo01 = __halves2half2(__float2half(v.x - __half2float(h0)),
                                      __float2half(v.y - __half2float(h1)));
        __half2 lo23 = __halves2half2(__float2half(v.z - __half2float(h2)),
                                      __float2half(v.w - __half2float(h3)));
        size_t o = (size_t)row * d + 4 * c;
        *(__half2*)(g_Ehi + o) = hi01; *(__half2*)(g_Ehi + o + 2) = hi23;
        *(__half2*)(g_Elo + o) = lo01; *(__half2*)(g_Elo + o + 2) = lo23;
    }
    for (int o = 16; o; o >>= 1) s += __shfl_xor_sync(0xffffffffu, s, o);
    __shared__ float ws[4];
    int lane = t & 31, w = t >> 5;
    if (lane == 0) ws[w] = s;
    __syncthreads();
    if (t == 0) {
        float tot = 0.f;
        for (int k = 0; k < (int)(blockDim.x >> 5); k++) tot += ws[k];
        g_sq[row] = tot;
        g_hnfb[row] = 0u;
        g_hnsemi[row] = __float_as_uint(BIGD2);
        if (row == 0) g_semiflag = 0;
    }
}

// ---------------- kernel 1: hist + scan + fill (single block) ----------------
__global__ void classlist_kernel(const int* __restrict__ labels, int n) {
    __shared__ int cnt[NB];
    __shared__ int s[NB];
    __shared__ int cur[NB];
    int t = threadIdx.x;
    cnt[t] = 0;
    __syncthreads();
    for (int i = t; i < n; i += blockDim.x) atomicAdd(&cnt[labels[i] & (NB - 1)], 1);
    __syncthreads();
    int v = cnt[t];
    s[t] = v;
    for (int off = 1; off < NB; off <<= 1) {
        __syncthreads();
        int u = (t >= off) ? s[t - off] : 0;
        __syncthreads();
        s[t] += u;
    }
    __syncthreads();
    int excl = s[t] - v;
    g_coff[t] = excl;
    g_ccount[t] = v;
    cur[t] = excl;
    __syncthreads();
    for (int i = t; i < n; i += blockDim.x) {
        int c = labels[i] & (NB - 1);
        int pos = atomicAdd(&cur[c], 1);
        g_clist[pos] = i;
    }
}

// ---------------- kernel 2: exact fp32 hardest positive (1 warp / anchor) ----------------
__global__ void hp_kernel(const float* __restrict__ E, const int* __restrict__ labels,
                          int n, int d) {
    int w = (blockIdx.x * blockDim.x + threadIdx.x) >> 5;
    int lid = threadIdx.x & 31;
    if (w >= n) return;
    int c = labels[w] & (NB - 1);
    const float4* ea = (const float4*)(E + (size_t)w * d);
    int dk4 = d >> 7;
    float4 a0[MAXD / 128];
#pragma unroll
    for (int j = 0; j < MAXD / 128; j++) if (j < dk4) a0[j] = ea[lid + 32 * j];
    int beg = g_coff[c], cnt = g_ccount[c];
    float sqa = g_sq[w];
    float maxd2 = 0.f;
    for (int t = 0; t < cnt; t++) {
        int m = g_clist[beg + t];
        const float4* em = (const float4*)(E + (size_t)m * d);
        float dot = 0.f;
#pragma unroll
        for (int j = 0; j < MAXD / 128; j++)
            if (j < dk4) {
                float4 b = em[lid + 32 * j];
                dot += a0[j].x * b.x + a0[j].y * b.y + a0[j].z * b.z + a0[j].w * b.w;
            }
        for (int o = 16; o; o >>= 1) dot += __shfl_xor_sync(0xffffffffu, dot, o);
        float d2 = sqa + g_sq[m] - 2.f * dot;
        maxd2 = fmaxf(maxd2, d2);
    }
    if (lid == 0) {
        float h2 = fmaxf(maxd2, 1e-12f);
        g_hp2[w] = h2;
        float hp = sqrtf(h2);
        g_hpB2[w] = (hp + MARGIN) * (hp + MARGIN);
    }
}

// ---------------- kernel 3: HMMA GEMM (2-product split), 512 thr, 3-stage, 1 barrier/chunk --
#define BK      32                    // halves per k-chunk (64 bytes)
#define TILEB   8192                  // 128 rows * 64 B
#define STAGEB  (3 * TILEB)           // Ahi, Bhi, Blo = 24 KB
#define AUXO    (3 * STAGEB)          // 73728
#define SMEM_DYN (AUXO + 6144)

__global__ __launch_bounds__(512, 1) void gemm_kernel(const int* __restrict__ labels,
                                                      int n, int d) {
    extern __shared__ char sm[];
    uint32_t sb = smem_u32(sm);
    int tid = threadIdx.x, lane = tid & 31, wid = tid >> 5;
    int wm = wid >> 2, wn = wid & 3;   // 4x4 warp grid; warp tile 32x32

    // triangle mapping: bid -> (by, bx), bx <= by
    int bid = blockIdx.x;
    int by = (int)((sqrtf(8.f * (float)bid + 1.f) - 1.f) * 0.5f);
    while ((by + 1) * (by + 2) / 2 <= bid) by++;
    while (by * (by + 1) / 2 > bid) by--;
    int bx = bid - by * (by + 1) / 2;
    int rowBase = by * 128, colBase = bx * 128;

    float*    s_sqc  = (float*)(sm + AUXO);
    int*      s_labc = (int*)(sm + AUXO + 512);
    float*    s_sqr  = (float*)(sm + AUXO + 1024);
    int*      s_labr = (int*)(sm + AUXO + 1536);
    float*    s_hp2r = (float*)(sm + AUXO + 2048);
    float*    s_hpBr = (float*)(sm + AUXO + 2560);
    float*    s_hp2c = (float*)(sm + AUXO + 3072);
    float*    s_hpBc = (float*)(sm + AUXO + 3584);
    unsigned* shRmax = (unsigned*)(sm + AUXO + 4096);
    unsigned* shRmin = (unsigned*)(sm + AUXO + 4608);
    unsigned* shCmax = (unsigned*)(sm + AUXO + 5120);
    unsigned* shCmin = (unsigned*)(sm + AUXO + 5632);

    if (tid < 128) {
        s_sqc[tid]  = g_sq[colBase + tid];  s_labc[tid] = labels[colBase + tid];
        s_sqr[tid]  = g_sq[rowBase + tid];  s_labr[tid] = labels[rowBase + tid];
        s_hp2r[tid] = g_hp2[rowBase + tid]; s_hpBr[tid] = g_hpB2[rowBase + tid];
        s_hp2c[tid] = g_hp2[colBase + tid]; s_hpBc[tid] = g_hpB2[colBase + tid];
        shRmax[tid] = 0u; shRmin[tid] = __float_as_uint(BIGD2);
        shCmax[tid] = 0u; shCmin[tid] = __float_as_uint(BIGD2);
    }

    // cp.async: 3 tiles x 512 chunks(16B) per stage / 512 threads = 3 per thread
    const __half* gsrc[3];
    uint32_t sdst[3];
    {
        const __half* tps[3] = {g_Ehi + (size_t)rowBase * d,   // A hi (rows)
                                g_Ehi + (size_t)colBase * d,   // B hi (cols)
                                g_Elo + (size_t)colBase * d};  // B lo (cols)
        int r = tid >> 2, ch = tid & 3;
#pragma unroll
        for (int t = 0; t < 3; t++) {
            gsrc[t] = tps[t] + (size_t)r * d + ch * 8;
            sdst[t] = sb + t * TILEB + r * 64 + (((ch + (r >> 1)) & 3) << 4);
        }
    }

    // per-lane swizzled ldmatrix addresses
    int r0A = wm * 32 + (lane & 15);
    int cA  = lane >> 4;
    uint32_t aoff0 = (uint32_t)(r0A * 64 + (((cA + (r0A >> 1)) & 3) << 4));
    uint32_t aoff1 = (uint32_t)(r0A * 64 + (((cA + 2 + (r0A >> 1)) & 3) << 4));
    int r0B = wn * 32 + (lane & 7) + ((lane >> 4) & 1) * 8;
    int cB  = (lane >> 3) & 1;
    uint32_t boff0 = (uint32_t)(r0B * 64 + (((cB + (r0B >> 1)) & 3) << 4));
    uint32_t boff1 = (uint32_t)(r0B * 64 + (((cB + 2 + (r0B >> 1)) & 3) << 4));

    float acc[2][4][4];
#pragma unroll
    for (int im = 0; im < 2; im++)
#pragma unroll
        for (int in = 0; in < 4; in++)
#pragma unroll
            for (int e = 0; e < 4; e++) acc[im][in][e] = 0.f;

    int NC = d / BK;   // 16

    // prologue: stages 0 and 1
#pragma unroll
    for (int t = 0; t < 3; t++) CP_ASYNC16(sdst[t], gsrc[t]);
    CP_COMMIT();
#pragma unroll
    for (int t = 0; t < 3; t++) CP_ASYNC16(sdst[t] + STAGEB, gsrc[t] + BK);
    CP_COMMIT();

    int cb = 0, ib = 2;
    for (int c = 0; c < NC; c++) {
        if (c + 1 < NC) { CP_WAIT1(); } else { CP_WAIT0(); }
        __syncthreads();                           // stage cb visible; stage ib free
        if (c + 2 < NC) {
            int k0 = (c + 2) * BK;
            uint32_t so = (uint32_t)ib * STAGEB;
#pragma unroll
            for (int t = 0; t < 3; t++) CP_ASYNC16(sdst[t] + so, gsrc[t] + k0);
            CP_COMMIT();
            ib = (ib == 2) ? 0 : ib + 1;
        }

        uint32_t base = sb + (uint32_t)cb * STAGEB;
        uint32_t ah[2][2][4], bh[2][4][2], bl[2][4][2];
#pragma unroll
        for (int k16 = 0; k16 < 2; k16++) {
            uint32_t ao = k16 ? aoff1 : aoff0;
            uint32_t bo = k16 ? boff1 : boff0;
#pragma unroll
            for (int im = 0; im < 2; im++) {
                uint32_t aA = base + im * 1024 + ao;
                LDM4(ah[k16][im][0], ah[k16][im][1], ah[k16][im][2], ah[k16][im][3], aA);
            }
#pragma unroll
            for (int p = 0; p < 2; p++) {
                uint32_t aB = base + TILEB + p * 1024 + bo;
                LDM4(bh[k16][2 * p][0], bh[k16][2 * p][1],
                     bh[k16][2 * p + 1][0], bh[k16][2 * p + 1][1], aB);
                LDM4(bl[k16][2 * p][0], bl[k16][2 * p][1],
                     bl[k16][2 * p + 1][0], bl[k16][2 * p + 1][1], aB + TILEB);
            }
        }
#pragma unroll
        for (int k16 = 0; k16 < 2; k16++)
#pragma unroll
            for (int im = 0; im < 2; im++)
#pragma unroll
                for (int in = 0; in < 4; in++) {
                    MMA16816(acc[im][in], ah[k16][im], bh[k16][in][0], bh[k16][in][1]);
                    MMA16816(acc[im][in], ah[k16][im], bl[k16][in][0], bl[k16][in][1]);
                }
        cb = (cb == 2) ? 0 : cb + 1;
    }

    // ---- epilogue: row-side ----
#pragma unroll
    for (int im = 0; im < 2; im++)
#pragma unroll
        for (int eh = 0; eh < 2; eh++) {
            int rloc = wm * 32 + im * 16 + (lane >> 2) + eh * 8;
            float sqr = s_sqr[rloc];
            int   labr = s_labr[rloc];
            float A = s_hp2r[rloc], B = s_hpBr[rloc];
            float mx = 0.f, mn = BIGD2;
#pragma unroll
            for (int in = 0; in < 4; in++)
#pragma unroll
                for (int ec = 0; ec < 2; ec++) {
                    int cloc = wn * 32 + in * 8 + (lane & 3) * 2 + ec;
                    float dot = acc[im][in][eh * 2 + ec];
                    float d2 = fmaxf(sqr + s_sqc[cloc] - 2.f * dot, 1e-12f);
                    if (labr != s_labc[cloc]) {
                        mx = fmaxf(mx, d2);
                        if (d2 > A && d2 < B) mn = fminf(mn, d2);
                    }
                }
            if (mx > 0.f) atomicMax(&shRmax[rloc], __float_as_uint(mx));
            if (mn < BIGD2) atomicMin(&shRmin[rloc], __float_as_uint(mn));
        }

    // ---- epilogue: col-side (symmetric) ----
#pragma unroll
    for (int in = 0; in < 4; in++)
#pragma unroll
        for (int ec = 0; ec < 2; ec++) {
            int cloc = wn * 32 + in * 8 + (lane & 3) * 2 + ec;
            float sqc = s_sqc[cloc];
            int   labc = s_labc[cloc];
            float A = s_hp2c[cloc], B = s_hpBc[cloc];
            float mx = 0.f, mn = BIGD2;
#pragma unroll
            for (int im = 0; im < 2; im++)
#pragma unroll
                for (int eh = 0; eh < 2; eh++) {
                    int rloc = wm * 32 + im * 16 + (lane >> 2) + eh * 8;
                    float dot = acc[im][in][eh * 2 + ec];
                    float d2 = fmaxf(s_sqr[rloc] + sqc - 2.f * dot, 1e-12f);
                    if (labc != s_labr[rloc]) {
                        mx = fmaxf(mx, d2);
                        if (d2 > A && d2 < B) mn = fminf(mn, d2);
                    }
                }
            if (mx > 0.f) atomicMax(&shCmax[cloc], __float_as_uint(mx));
            if (mn < BIGD2) atomicMin(&shCmin[cloc], __float_as_uint(mn));
        }

    __syncthreads();
    if (tid < 128) {
        if (shRmax[tid]) atomicMax(&g_hnfb[rowBase + tid], shRmax[tid]);
        if (shRmin[tid] != __float_as_uint(BIGD2)) {
            atomicMin(&g_hnsemi[rowBase + tid], shRmin[tid]);
            g_semiflag = 1;
        }
        if (shCmax[tid]) atomicMax(&g_hnfb[colBase + tid], shCmax[tid]);
        if (shCmin[tid] != __float_as_uint(BIGD2)) {
            atomicMin(&g_hnsemi[colBase + tid], shCmin[tid]);
            g_semiflag = 1;
        }
    }
}

// ---------------- kernel 4: finalize ----------------
__global__ void finalize_kernel(float* __restrict__ out, int n) {
    bool useSemi = (g_semiflag != 0);
    float sum = 0.f;
    int cnt = 0;
    for (int i = threadIdx.x; i < n; i += blockDim.x) {
        float hp = sqrtf(g_hp2[i]);
        unsigned hb = useSemi ? g_hnsemi[i] : g_hnfb[i];
        float hn = sqrtf(__uint_as_float(hb));
        float t = hp - hn + MARGIN;
        if (t < 0.f) t = 0.f;
        sum += t;
        if (t > 0.f) cnt++;
    }
    for (int o = 16; o; o >>= 1) {
        sum += __shfl_xor_sync(0xffffffffu, sum, o);
        cnt += __shfl_xor_sync(0xffffffffu, cnt, o);
    }
    __shared__ float wsum[32];
    __shared__ int wcnt[32];
    int lane = threadIdx.x & 31, w = threadIdx.x >> 5;
    if (lane == 0) { wsum[w] = sum; wcnt[w] = cnt; }
    __syncthreads();
    if (threadIdx.x == 0) {
        float s = 0.f; int c = 0;
        for (int k = 0; k < (int)(blockDim.x >> 5); k++) { s += wsum[k]; c += wcnt[k]; }
        out[0] = (c > 0) ? (s / (float)c) : 0.0f;
    }
}

// ---------------- launch ----------------
extern "C" void kernel_launch(void* const* d_in, const int* in_sizes, int n_in,
                              void* d_out, int out_size) {
    const float* E = (const float*)d_in[0];
    const int* labels = (const int*)d_in[1];
    int n = in_sizes[1];
    int d = in_sizes[0] / n;

    cudaFuncSetAttribute(gemm_kernel, cudaFuncAttributeMaxDynamicSharedMemorySize, SMEM_DYN);

    convsq_kernel<<<n, 128>>>(E, d);                       // launch 0
    classlist_kernel<<<1, NB>>>(labels, n);                // launch 1
    hp_kernel<<<n / 4, 128>>>(E, labels, n, d);            // launch 2
    int nb = n / 128;
    gemm_kernel<<<nb * (nb + 1) / 2, 512, SMEM_DYN>>>(labels, n, d);  // launch 3 (profiled)
    finalize_kernel<<<1, 1024>>>((float*)d_out, n);        // launch 4
}